// round 1
// baseline (speedup 1.0000x reference)
#include <cuda_runtime.h>
#include <math.h>

#define BATCH   128
#define EMBED   512
#define HIDDEN  512
#define VOCAB   32000
#define TSTEPS  20
#define NVBLK   (VOCAB/128)   // 250 logits blocks

// Persistent scratch (re-initialized at the start of every kernel_launch)
__device__ float g_xh[BATCH * 1024];      // [b][0:512]=x, [b][512:1024]=h
__device__ float g_c[BATCH * HIDDEN];
__device__ float g_gates[BATCH * 2048];   // [b][4H], gate order i,f,g,o
__device__ float g_pval[NVBLK * BATCH];
__device__ int   g_pidx[NVBLK * BATCH];

__device__ __forceinline__ float sigf(float x) { return 1.0f / (1.0f + expf(-x)); }

// ---------------------------------------------------------------------------
__global__ void init_kernel(const float* __restrict__ features) {
    int b = blockIdx.x, t = threadIdx.x;
    for (int k = t; k < 512; k += 256) {
        g_xh[b * 1024 + k]       = features[b * 512 + k];
        g_xh[b * 1024 + 512 + k] = 0.0f;
        g_c[b * 512 + k]         = 0.0f;
    }
}

// ---------------------------------------------------------------------------
// gates[n][m] = sum_k xh[n][k] * Wcat[m][k] + bih[m] + bhh[m]
// Wcat[m][k] = W_ih[m][k] for k<512, W_hh[m][k-512] for k>=512.
// Tile: 64 out-rows x 32 batch, BK=16, 128 threads (4x4 micro-tile).
__global__ __launch_bounds__(128) void gates_kernel(
    const float* __restrict__ Wih, const float* __restrict__ Whh,
    const float* __restrict__ bih, const float* __restrict__ bhh) {
    __shared__ float As[16][65];
    __shared__ float Bs[16][33];
    const int m0 = blockIdx.x * 64;
    const int n0 = blockIdx.y * 32;
    const int tid = threadIdx.x;
    const int lr = tid >> 2;            // 0..31
    const int lc = (tid & 3) * 4;       // 0,4,8,12
    const int tr = tid >> 3;            // 0..15 -> 4 out rows each
    const int tc = tid & 7;             // 0..7  -> 4 batch cols each
    float acc[4][4] = {};

    for (int k0 = 0; k0 < 1024; k0 += 16) {
        const float* W = (k0 < 512) ? Wih : Whh;
        const int kc = (k0 < 512) ? k0 : (k0 - 512);
        float4 a0 = *(const float4*)(W + (size_t)(m0 + lr) * 512 + kc + lc);
        float4 a1 = *(const float4*)(W + (size_t)(m0 + 32 + lr) * 512 + kc + lc);
        float4 b0 = *(const float4*)(g_xh + (size_t)(n0 + lr) * 1024 + k0 + lc);
        __syncthreads();
        As[lc + 0][lr] = a0.x; As[lc + 1][lr] = a0.y;
        As[lc + 2][lr] = a0.z; As[lc + 3][lr] = a0.w;
        As[lc + 0][32 + lr] = a1.x; As[lc + 1][32 + lr] = a1.y;
        As[lc + 2][32 + lr] = a1.z; As[lc + 3][32 + lr] = a1.w;
        Bs[lc + 0][lr] = b0.x; Bs[lc + 1][lr] = b0.y;
        Bs[lc + 2][lr] = b0.z; Bs[lc + 3][lr] = b0.w;
        __syncthreads();
#pragma unroll
        for (int kk = 0; kk < 16; ++kk) {
            float av[4], bv[4];
#pragma unroll
            for (int i = 0; i < 4; ++i) av[i] = As[kk][tr * 4 + i];
#pragma unroll
            for (int j = 0; j < 4; ++j) bv[j] = Bs[kk][tc * 4 + j];
#pragma unroll
            for (int i = 0; i < 4; ++i)
#pragma unroll
                for (int j = 0; j < 4; ++j) acc[i][j] = fmaf(av[i], bv[j], acc[i][j]);
        }
    }
#pragma unroll
    for (int i = 0; i < 4; ++i) {
        int m = m0 + tr * 4 + i;
        float bb = bih[m] + bhh[m];
#pragma unroll
        for (int j = 0; j < 4; ++j) {
            int n = n0 + tc * 4 + j;
            g_gates[(size_t)n * 2048 + m] = acc[i][j] + bb;
        }
    }
}

// ---------------------------------------------------------------------------
__global__ void lstm_pw_kernel() {
    int b = blockIdx.x, j = threadIdx.x;
    const float* g = g_gates + (size_t)b * 2048;
    float ig = sigf(g[j]);
    float fg = sigf(g[512 + j]);
    float gg = tanhf(g[1024 + j]);
    float og = sigf(g[1536 + j]);
    float c = fg * g_c[b * 512 + j] + ig * gg;
    g_c[b * 512 + j] = c;
    g_xh[b * 1024 + 512 + j] = og * tanhf(c);
}

// ---------------------------------------------------------------------------
// logits[v][n] = sum_k Wfc[v][k] * h[n][k] + bfc[v]; partial argmax per batch col.
// Tile: 128 vocab x 128 batch, BK=8, 256 threads (8x8 micro-tile), 2 CTAs/SM.
__global__ __launch_bounds__(256, 2) void logits_kernel(
    const float* __restrict__ Wfc, const float* __restrict__ bfc) {
    __shared__ float As[8][132];
    __shared__ float Bs[8][132];
    __shared__ float rv[16][128];
    __shared__ int   ri[16][128];
    const int vb = blockIdx.x * 128;
    const int tid = threadIdx.x;
    const int ar = tid >> 1;            // 0..127
    const int ac = (tid & 1) * 4;       // 0 or 4
    const int tr = tid >> 4;            // 0..15 vocab groups
    const int tc = tid & 15;            // 0..15 batch groups
    float acc[8][8] = {};
    const float* hbase = g_xh + 512;    // h[n][k] = hbase[n*1024 + k]

    for (int k0 = 0; k0 < 512; k0 += 8) {
        float4 a = *(const float4*)(Wfc + (size_t)(vb + ar) * 512 + k0 + ac);
        float4 b = *(const float4*)(hbase + (size_t)ar * 1024 + k0 + ac);
        __syncthreads();
        As[ac + 0][ar] = a.x; As[ac + 1][ar] = a.y;
        As[ac + 2][ar] = a.z; As[ac + 3][ar] = a.w;
        Bs[ac + 0][ar] = b.x; Bs[ac + 1][ar] = b.y;
        Bs[ac + 2][ar] = b.z; Bs[ac + 3][ar] = b.w;
        __syncthreads();
#pragma unroll
        for (int kk = 0; kk < 8; ++kk) {
            float4 a0 = *(const float4*)&As[kk][tr * 8];
            float4 a1 = *(const float4*)&As[kk][tr * 8 + 4];
            float4 b0 = *(const float4*)&Bs[kk][tc * 8];
            float4 b1 = *(const float4*)&Bs[kk][tc * 8 + 4];
            float av[8] = {a0.x, a0.y, a0.z, a0.w, a1.x, a1.y, a1.z, a1.w};
            float bv[8] = {b0.x, b0.y, b0.z, b0.w, b1.x, b1.y, b1.z, b1.w};
#pragma unroll
            for (int i = 0; i < 8; ++i)
#pragma unroll
                for (int j = 0; j < 8; ++j) acc[i][j] = fmaf(av[i], bv[j], acc[i][j]);
        }
    }

    float bb[8];
#pragma unroll
    for (int i = 0; i < 8; ++i) bb[i] = bfc[vb + tr * 8 + i];
#pragma unroll
    for (int j = 0; j < 8; ++j) {
        float best = acc[0][j] + bb[0];
        int bidx = vb + tr * 8;
#pragma unroll
        for (int i = 1; i < 8; ++i) {
            float v = acc[i][j] + bb[i];
            if (v > best) { best = v; bidx = vb + tr * 8 + i; }  // strict >: first occurrence
        }
        rv[tr][tc * 8 + j] = best;
        ri[tr][tc * 8 + j] = bidx;
    }
    __syncthreads();
    if (tid < 128) {
        float best = rv[0][tid];
        int bidx = ri[0][tid];
#pragma unroll
        for (int r = 1; r < 16; ++r) {
            float v = rv[r][tid]; int ix = ri[r][tid];
            if (v > best || (v == best && ix < bidx)) { best = v; bidx = ix; }
        }
        g_pval[(size_t)blockIdx.x * 128 + tid] = best;
        g_pidx[(size_t)blockIdx.x * 128 + tid] = bidx;
    }
}

// ---------------------------------------------------------------------------
// Final argmax over 250 partials per batch row; write outputs; gather embedding.
__global__ void reduce_kernel(const float* __restrict__ emb,
                              float* __restrict__ out, int step) {
    __shared__ float sv[256];
    __shared__ int   si[256];
    const int b = blockIdx.x, t = threadIdx.x;
    float bv = -INFINITY;
    int bi = 0x7fffffff;
    if (t < NVBLK) { bv = g_pval[(size_t)t * 128 + b]; bi = g_pidx[(size_t)t * 128 + b]; }
    sv[t] = bv; si[t] = bi;
    __syncthreads();
    for (int s = 128; s > 0; s >>= 1) {
        if (t < s) {
            float v = sv[t + s]; int ix = si[t + s];
            if (v > sv[t] || (v == sv[t] && ix < si[t])) { sv[t] = v; si[t] = ix; }
        }
        __syncthreads();
    }
    const int idx = si[0];
    if (t == 0) {
        out[b * TSTEPS + step] = (float)idx;                    // ids [B,T]
        out[BATCH * TSTEPS + b * TSTEPS + step] = sv[0];        // vals [B,T]
    }
    for (int k = t; k < 512; k += 256)
        g_xh[b * 1024 + k] = emb[(size_t)idx * 512 + k];
}

// ---------------------------------------------------------------------------
extern "C" void kernel_launch(void* const* d_in, const int* in_sizes, int n_in,
                              void* d_out, int out_size) {
    const float* features = (const float*)d_in[0];
    // d_in[1] = lengths (unused; always MAX_SEQ_LEN)
    const float* emb = (const float*)d_in[2];
    const float* Wih = (const float*)d_in[3];
    const float* Whh = (const float*)d_in[4];
    const float* bih = (const float*)d_in[5];
    const float* bhh = (const float*)d_in[6];
    const float* Wfc = (const float*)d_in[7];
    const float* bfc = (const float*)d_in[8];
    float* out = (float*)d_out;

    init_kernel<<<BATCH, 256>>>(features);
    for (int t = 0; t < TSTEPS; ++t) {
        gates_kernel<<<dim3(32, 4), 128>>>(Wih, Whh, bih, bhh);
        lstm_pw_kernel<<<BATCH, 512>>>();
        logits_kernel<<<NVBLK, 256>>>(Wfc, bfc);
        reduce_kernel<<<BATCH, 256>>>(emb, out, t);
    }
}

// round 3
// speedup vs baseline: 1.3441x; 1.3441x over previous
#include <cuda_runtime.h>
#include <cuda_fp16.h>
#include <math.h>
#include <stdint.h>

#define BATCH   128
#define EMBED   512
#define HIDDEN  512
#define VOCAB   32000
#define TSTEPS  20
#define NVBLK   (VOCAB/128)   // 250 logits blocks

// ---------------------------------------------------------------------------
// Persistent device scratch (re-written every launch -> deterministic)
__device__ float  g_xh[BATCH * 1024];      // [b][0:512]=x, [b][512:1024]=h (fp32)
__device__ float  g_c[BATCH * HIDDEN];
__device__ float  g_gates[BATCH * 2048];
__device__ float  g_pval[NVBLK * BATCH];
__device__ int    g_pidx[NVBLK * BATCH];
__device__ __half g_W1[VOCAB * 512];       // hi split of W_fc
__device__ __half g_W2[VOCAB * 512];       // (W - W1) * 1024
__device__ __half g_h1[BATCH * 512];       // hi split of h
__device__ __half g_h2[BATCH * 512];       // (h - h1) * 1024

__device__ __forceinline__ float sigf(float x) { return 1.0f / (1.0f + expf(-x)); }

// ---------------------------------------------------------------------------
__device__ __forceinline__ uint32_t smem_u32(const void* p) {
    uint32_t a;
    asm("{ .reg .u64 t; cvta.to.shared.u64 t, %1; cvt.u32.u64 %0, t; }" : "=r"(a) : "l"(p));
    return a;
}
__device__ __forceinline__ void cp16(uint32_t dst, const void* src) {
    asm volatile("cp.async.cg.shared.global [%0], [%1], 16;" :: "r"(dst), "l"(src) : "memory");
}
#define CP_COMMIT() asm volatile("cp.async.commit_group;" ::: "memory")
template <int N> __device__ __forceinline__ void cp_wait() {
    asm volatile("cp.async.wait_group %0;" :: "n"(N) : "memory");
}
__device__ __forceinline__ void ldsm4(uint32_t* r, uint32_t a) {
    asm volatile("ldmatrix.sync.aligned.m8n8.x4.shared.b16 {%0,%1,%2,%3}, [%4];"
                 : "=r"(r[0]), "=r"(r[1]), "=r"(r[2]), "=r"(r[3]) : "r"(a));
}
__device__ __forceinline__ void mma16816(float* d, const uint32_t* a, const uint32_t* b) {
    asm volatile(
        "mma.sync.aligned.m16n8k16.row.col.f32.f16.f16.f32 "
        "{%0,%1,%2,%3}, {%4,%5,%6,%7}, {%8,%9}, {%0,%1,%2,%3};"
        : "+f"(d[0]), "+f"(d[1]), "+f"(d[2]), "+f"(d[3])
        : "r"(a[0]), "r"(a[1]), "r"(a[2]), "r"(a[3]), "r"(b[0]), "r"(b[1]));
}

// ---------------------------------------------------------------------------
__global__ void init_kernel(const float* __restrict__ features) {
    int b = blockIdx.x, t = threadIdx.x;
    for (int k = t; k < 512; k += 256) {
        g_xh[b * 1024 + k]       = features[b * 512 + k];
        g_xh[b * 1024 + 512 + k] = 0.0f;
        g_c[b * 512 + k]         = 0.0f;
        g_h1[b * 512 + k]        = __float2half_rn(0.0f);
        g_h2[b * 512 + k]        = __float2half_rn(0.0f);
    }
}

// Split W_fc -> (W1, W2*1024) fp16, once per launch. 4,096,000 float4s.
__global__ void wsplit_kernel(const float* __restrict__ Wfc) {
    size_t i = (size_t)blockIdx.x * blockDim.x + threadIdx.x;
    float4 v = ((const float4*)Wfc)[i];
    __half a0 = __float2half_rn(v.x), a1 = __float2half_rn(v.y);
    __half a2 = __float2half_rn(v.z), a3 = __float2half_rn(v.w);
    __half b0 = __float2half_rn((v.x - __half2float(a0)) * 1024.0f);
    __half b1 = __float2half_rn((v.y - __half2float(a1)) * 1024.0f);
    __half b2 = __float2half_rn((v.z - __half2float(a2)) * 1024.0f);
    __half b3 = __float2half_rn((v.w - __half2float(a3)) * 1024.0f);
    __half2* w1 = (__half2*)g_W1;
    __half2* w2 = (__half2*)g_W2;
    w1[i * 2]     = __halves2half2(a0, a1);
    w1[i * 2 + 1] = __halves2half2(a2, a3);
    w2[i * 2]     = __halves2half2(b0, b1);
    w2[i * 2 + 1] = __halves2half2(b2, b3);
}

// ---------------------------------------------------------------------------
// gates[n][m] = sum_k xh[n][k] * Wcat[m][k] + bias[m]   (fp32)
__global__ __launch_bounds__(128) void gates_kernel(
    const float* __restrict__ Wih, const float* __restrict__ Whh,
    const float* __restrict__ bih, const float* __restrict__ bhh) {
    __shared__ float As[16][65];
    __shared__ float Bs[16][33];
    const int m0 = blockIdx.x * 64;
    const int n0 = blockIdx.y * 32;
    const int tid = threadIdx.x;
    const int lr = tid >> 2;
    const int lc = (tid & 3) * 4;
    const int tr = tid >> 3;
    const int tc = tid & 7;
    float acc[4][4] = {};

    for (int k0 = 0; k0 < 1024; k0 += 16) {
        const float* W = (k0 < 512) ? Wih : Whh;
        const int kc = (k0 < 512) ? k0 : (k0 - 512);
        float4 a0 = *(const float4*)(W + (size_t)(m0 + lr) * 512 + kc + lc);
        float4 a1 = *(const float4*)(W + (size_t)(m0 + 32 + lr) * 512 + kc + lc);
        float4 b0 = *(const float4*)(g_xh + (size_t)(n0 + lr) * 1024 + k0 + lc);
        __syncthreads();
        As[lc + 0][lr] = a0.x; As[lc + 1][lr] = a0.y;
        As[lc + 2][lr] = a0.z; As[lc + 3][lr] = a0.w;
        As[lc + 0][32 + lr] = a1.x; As[lc + 1][32 + lr] = a1.y;
        As[lc + 2][32 + lr] = a1.z; As[lc + 3][32 + lr] = a1.w;
        Bs[lc + 0][lr] = b0.x; Bs[lc + 1][lr] = b0.y;
        Bs[lc + 2][lr] = b0.z; Bs[lc + 3][lr] = b0.w;
        __syncthreads();
#pragma unroll
        for (int kk = 0; kk < 16; ++kk) {
            float av[4], bv[4];
#pragma unroll
            for (int i = 0; i < 4; ++i) av[i] = As[kk][tr * 4 + i];
#pragma unroll
            for (int j = 0; j < 4; ++j) bv[j] = Bs[kk][tc * 4 + j];
#pragma unroll
            for (int i = 0; i < 4; ++i)
#pragma unroll
                for (int j = 0; j < 4; ++j) acc[i][j] = fmaf(av[i], bv[j], acc[i][j]);
        }
    }
#pragma unroll
    for (int i = 0; i < 4; ++i) {
        int m = m0 + tr * 4 + i;
        float bb = bih[m] + bhh[m];
#pragma unroll
        for (int j = 0; j < 4; ++j) {
            int n = n0 + tc * 4 + j;
            g_gates[(size_t)n * 2048 + m] = acc[i][j] + bb;
        }
    }
}

// ---------------------------------------------------------------------------
// LSTM pointwise + fp16 split of h
__global__ void lstm_pw_kernel() {
    int b = blockIdx.x, j = threadIdx.x;
    const float* g = g_gates + (size_t)b * 2048;
    float ig = sigf(g[j]);
    float fg = sigf(g[512 + j]);
    float gg = tanhf(g[1024 + j]);
    float og = sigf(g[1536 + j]);
    float c = fg * g_c[b * 512 + j] + ig * gg;
    g_c[b * 512 + j] = c;
    float h = og * tanhf(c);
    g_xh[b * 1024 + 512 + j] = h;
    __half a = __float2half_rn(h);
    g_h1[b * 512 + j] = a;
    g_h2[b * 512 + j] = __float2half_rn((h - __half2float(a)) * 1024.0f);
}

// ---------------------------------------------------------------------------
// HMMA logits: per CTA 128 vocab x 128 batch, K=512.
// D0 += W1*h1 ; D1 += W1*h2' + W2'*h1 ; logit = D0 + D1/1024 + bias.
// smem: 2 stages x 4 tiles (W1,W2,h1,h2), each tile 128 rows x 32 halves,
// rows padded to 80B (conflict-free ldmatrix). Epilogue reuses stage smem.
#define KC      32
#define ROWB    80
#define TILEB   (128 * ROWB)       // 10240
#define STAGEB  (4 * TILEB)        // 40960
#define SMEM_LOG (2 * STAGEB)      // 81920

__global__ __launch_bounds__(256, 1) void logits_mma_kernel(const float* __restrict__ bfc) {
    extern __shared__ char smem[];
    const uint32_t sb = smem_u32(smem);
    const int tid = threadIdx.x;
    const int wid = tid >> 5;
    const int lane = tid & 31;
    const int vb = blockIdx.x * 128;
    const int vrow0 = (wid & 1) * 64;
    const int brow0 = (wid >> 1) * 32;

    float d0[4][4][4] = {};
    float d1[4][4][4] = {};

    // ---- stage loader: 2048 granules of 16B, 8 per thread ----
    auto load_stage = [&](int s, int k0) {
        const uint32_t st = sb + s * STAGEB;
        const __half* srcs[4] = { g_W1 + (size_t)vb * 512 + k0,
                                  g_W2 + (size_t)vb * 512 + k0,
                                  g_h1 + k0, g_h2 + k0 };
#pragma unroll
        for (int i = 0; i < 8; ++i) {
            int lin = i * 256 + tid;
            int t   = lin >> 9;
            int idx = lin & 511;
            int row = idx & 127;
            int col = idx >> 7;          // 0..3 (16B granules)
            cp16(st + t * TILEB + row * ROWB + col * 16,
                 srcs[t] + (size_t)row * 512 + col * 8);
        }
        CP_COMMIT();
    };

    load_stage(0, 0);
    load_stage(1, KC);

    for (int kc = 0; kc < 16; ++kc) {
        if (kc < 15) cp_wait<1>(); else cp_wait<0>();
        __syncthreads();
        const uint32_t st = sb + (kc & 1) * STAGEB;
#pragma unroll
        for (int ks = 0; ks < 2; ++ks) {
            const uint32_t kb = ks * 32;
            uint32_t a1[4][4], a2[4][4];
#pragma unroll
            for (int mi = 0; mi < 4; ++mi) {
                const int mat = lane >> 3;
                const uint32_t row = vrow0 + mi * 16 + (mat & 1) * 8 + (lane & 7);
                const uint32_t ao = row * ROWB + kb + (mat >> 1) * 16;
                ldsm4(a1[mi], st + 0 * TILEB + ao);
                ldsm4(a2[mi], st + 1 * TILEB + ao);
            }
            uint32_t b1[4][2], b2[4][2];
#pragma unroll
            for (int j = 0; j < 2; ++j) {
                const int mat = lane >> 3;
                const uint32_t row = brow0 + j * 16 + (mat >> 1) * 8 + (lane & 7);
                const uint32_t bo = row * ROWB + kb + (mat & 1) * 16;
                uint32_t r[4];
                ldsm4(r, st + 2 * TILEB + bo);
                b1[2 * j][0] = r[0]; b1[2 * j][1] = r[1];
                b1[2 * j + 1][0] = r[2]; b1[2 * j + 1][1] = r[3];
                ldsm4(r, st + 3 * TILEB + bo);
                b2[2 * j][0] = r[0]; b2[2 * j][1] = r[1];
                b2[2 * j + 1][0] = r[2]; b2[2 * j + 1][1] = r[3];
            }
#pragma unroll
            for (int mi = 0; mi < 4; ++mi)
#pragma unroll
                for (int nf = 0; nf < 4; ++nf) {
                    mma16816(d0[mi][nf], a1[mi], b1[nf]);
                    mma16816(d1[mi][nf], a1[mi], b2[nf]);
                    mma16816(d1[mi][nf], a2[mi], b1[nf]);
                }
        }
        __syncthreads();
        if (kc + 2 < 16) load_stage(kc & 1, (kc + 2) * KC);
    }

    // ---- epilogue: combine + bias into smem [b][v], then per-column argmax ----
    __syncthreads();
    float* slog = (float*)smem;                         // [128][132]
    float* pv   = (float*)(smem + 128 * 132 * 4);       // [256]
    int*   pi   = (int*)(smem + 128 * 132 * 4 + 1024);  // [256]
#pragma unroll
    for (int mi = 0; mi < 4; ++mi) {
        const int v0 = vrow0 + mi * 16 + (lane >> 2);
        const int v1 = v0 + 8;
        const float bias0 = bfc[vb + v0];
        const float bias1 = bfc[vb + v1];
#pragma unroll
        for (int nf = 0; nf < 4; ++nf) {
            const int b0 = brow0 + nf * 8 + 2 * (lane & 3);
            slog[(b0)     * 132 + v0] = d0[mi][nf][0] + d1[mi][nf][0] * 0.0009765625f + bias0;
            slog[(b0 + 1) * 132 + v0] = d0[mi][nf][1] + d1[mi][nf][1] * 0.0009765625f + bias0;
            slog[(b0)     * 132 + v1] = d0[mi][nf][2] + d1[mi][nf][2] * 0.0009765625f + bias1;
            slog[(b0 + 1) * 132 + v1] = d0[mi][nf][3] + d1[mi][nf][3] * 0.0009765625f + bias1;
        }
    }
    __syncthreads();
    {
        const int c = tid & 127;
        const int hh = tid >> 7;
        const float* col = slog + c * 132 + hh * 64;
        float bv = col[0];
        int bi = hh * 64;
#pragma unroll 8
        for (int v = 1; v < 64; ++v) {
            float x = col[v];
            if (x > bv) { bv = x; bi = hh * 64 + v; }
        }
        pv[tid] = bv; pi[tid] = bi;
    }
    __syncthreads();
    if (tid < 128) {
        float bv = pv[tid]; int bi = pi[tid];
        float v2 = pv[tid + 128]; int i2 = pi[tid + 128];
        if (v2 > bv || (v2 == bv && i2 < bi)) { bv = v2; bi = i2; }
        g_pval[(size_t)blockIdx.x * 128 + tid] = bv;
        g_pidx[(size_t)blockIdx.x * 128 + tid] = vb + bi;
    }
}

// ---------------------------------------------------------------------------
// Final argmax over 250 partials; write outputs; gather embedding.
__global__ void reduce_kernel(const float* __restrict__ emb,
                              float* __restrict__ out, int step) {
    __shared__ float sv[256];
    __shared__ int   si[256];
    const int b = blockIdx.x, t = threadIdx.x;
    float bv = -INFINITY;
    int bi = 0x7fffffff;
    if (t < NVBLK) { bv = g_pval[(size_t)t * 128 + b]; bi = g_pidx[(size_t)t * 128 + b]; }
    sv[t] = bv; si[t] = bi;
    __syncthreads();
    for (int s = 128; s > 0; s >>= 1) {
        if (t < s) {
            float v = sv[t + s]; int ix = si[t + s];
            if (v > sv[t] || (v == sv[t] && ix < si[t])) { sv[t] = v; si[t] = ix; }
        }
        __syncthreads();
    }
    const int idx = si[0];
    if (t == 0) {
        out[b * TSTEPS + step] = (float)idx;
        out[BATCH * TSTEPS + b * TSTEPS + step] = sv[0];
    }
    for (int k = t; k < 512; k += 256)
        g_xh[b * 1024 + k] = emb[(size_t)idx * 512 + k];
}

// ---------------------------------------------------------------------------
extern "C" void kernel_launch(void* const* d_in, const int* in_sizes, int n_in,
                              void* d_out, int out_size) {
    const float* features = (const float*)d_in[0];
    const float* emb = (const float*)d_in[2];
    const float* Wih = (const float*)d_in[3];
    const float* Whh = (const float*)d_in[4];
    const float* bih = (const float*)d_in[5];
    const float* bhh = (const float*)d_in[6];
    const float* Wfc = (const float*)d_in[7];
    const float* bfc = (const float*)d_in[8];
    float* out = (float*)d_out;

    cudaFuncSetAttribute(logits_mma_kernel,
                         cudaFuncAttributeMaxDynamicSharedMemorySize, SMEM_LOG);

    init_kernel<<<BATCH, 256>>>(features);
    wsplit_kernel<<<16000, 256>>>(Wfc);
    for (int t = 0; t < TSTEPS; ++t) {
        gates_kernel<<<dim3(32, 4), 128>>>(Wih, Whh, bih, bhh);
        lstm_pw_kernel<<<BATCH, 512>>>();
        logits_mma_kernel<<<NVBLK, 256, SMEM_LOG>>>(bfc);
        reduce_kernel<<<BATCH, 256>>>(emb, out, t);
    }
}